// round 10
// baseline (speedup 1.0000x reference)
#include <cuda_runtime.h>
#include <cuda_fp16.h>
#include <stdint.h>

// Flash attention, B=32, LQ=LK=2048, D=128, fp32 in/out. HMMA path.
// Mask: 4-byte elems (bool promoted); nonzero = masked. score=(q.k)*sqrt(128).
// QK^T: fp16 hi/lo 3-term MMA. PV: single-term fp16 (rel_err ~2.1e-4).
// R9: register-pressure attack. regs were capped at 255 -> hot-loop spills.
//  - no S double-buffer (pipeline was measured neutral)
//  - qa_lo lives in dedicated Q smem (reloaded via ldsm per iter), not regs
//  -> ~190 live regs, no spills.

namespace {

constexpr int B_   = 32;
constexpr int LQ_  = 2048;
constexpr int LK_  = 2048;
constexpr int DH   = 128;
constexpr int BR   = 128;
constexpr int BC   = 64;
constexpr int NTH  = 256;
constexpr int NIT  = LK_ / BC;
constexpr int RSB  = 272;              // 128 fp16 + 16B pad

constexpr int PLANE  = BC * RSB;       // 17408 B (64-row plane)
constexpr int QPLANE = BR * RSB;       // 34816 B (128-row plane)
constexpr int KSTG   = 2 * PLANE;      // K hi+lo stage

constexpr int SM_QHI = 0;                       // persistent Q hi
constexpr int SM_QLO = QPLANE;                  // persistent Q lo
constexpr int SM_K   = 2 * QPLANE;              // 2 K stages: 69632
constexpr int SM_V   = SM_K + 2 * KSTG;         // 2 V planes: 34816
constexpr int SM_MSK = SM_V + 2 * PLANE;        // 174080
constexpr int MROW   = 68;
constexpr int SM_TOT = SM_MSK + BR * MROW;      // 182784 B

__device__ __half g_khi[(size_t)B_ * LK_ * DH];
__device__ __half g_klo[(size_t)B_ * LK_ * DH];
__device__ __half g_vh [(size_t)B_ * LK_ * DH];

__device__ __forceinline__ uint32_t smem_u32(const void* p) {
    return (uint32_t)__cvta_generic_to_shared(p);
}
__device__ __forceinline__ void cp16(uint32_t dst, const void* src) {
    asm volatile("cp.async.cg.shared.global [%0], [%1], 16;" :: "r"(dst), "l"(src));
}
#define CP_COMMIT() asm volatile("cp.async.commit_group;")
#define CP_WAIT0()  asm volatile("cp.async.wait_group 0;")

__device__ __forceinline__ void ldsm4(uint32_t r[4], uint32_t a) {
    asm volatile("ldmatrix.sync.aligned.m8n8.x4.shared.b16 {%0,%1,%2,%3}, [%4];"
                 : "=r"(r[0]), "=r"(r[1]), "=r"(r[2]), "=r"(r[3]) : "r"(a));
}
__device__ __forceinline__ void ldsm4t(uint32_t r[4], uint32_t a) {
    asm volatile("ldmatrix.sync.aligned.m8n8.x4.trans.shared.b16 {%0,%1,%2,%3}, [%4];"
                 : "=r"(r[0]), "=r"(r[1]), "=r"(r[2]), "=r"(r[3]) : "r"(a));
}
__device__ __forceinline__ void mma_f16(float d[4], const uint32_t a[4], uint32_t b0, uint32_t b1) {
    asm volatile("mma.sync.aligned.m16n8k16.row.col.f32.f16.f16.f32 "
                 "{%0,%1,%2,%3}, {%4,%5,%6,%7}, {%8,%9}, {%0,%1,%2,%3};"
                 : "+f"(d[0]), "+f"(d[1]), "+f"(d[2]), "+f"(d[3])
                 : "r"(a[0]), "r"(a[1]), "r"(a[2]), "r"(a[3]), "r"(b0), "r"(b1));
}
__device__ __forceinline__ float ex2f(float x) {
    float y; asm("ex2.approx.f32 %0, %1;" : "=f"(y) : "f"(x)); return y;
}
__device__ __forceinline__ uint32_t bits2h(__half2 h) {
    uint32_t u; __builtin_memcpy(&u, &h, 4); return u;
}
__device__ __forceinline__ void split_store_h(float4 f, char* ph, char* pl) {
    __half h0 = __float2half_rn(f.x);
    __half h1 = __float2half_rn(f.y);
    __half h2 = __float2half_rn(f.z);
    __half h3 = __float2half_rn(f.w);
    *(__half2*)(ph)     = __halves2half2(h0, h1);
    *(__half2*)(ph + 4) = __halves2half2(h2, h3);
    __half l0 = __float2half_rn(f.x - __half2float(h0));
    __half l1 = __float2half_rn(f.y - __half2float(h1));
    __half l2 = __float2half_rn(f.z - __half2float(h2));
    __half l3 = __float2half_rn(f.w - __half2float(h3));
    *(__half2*)(pl)     = __halves2half2(l0, l1);
    *(__half2*)(pl + 4) = __halves2half2(l2, l3);
}
__device__ __forceinline__ uint32_t pack_h2(float x, float y) {
    return bits2h(__halves2half2(__float2half_rn(x), __float2half_rn(y)));
}

__global__ void __launch_bounds__(256, 4)
conv_kernel(const float* __restrict__ kg, const float* __restrict__ vg)
{
    size_t i4 = ((size_t)blockIdx.x * 256 + threadIdx.x) * 4;
    float4 fk = *(const float4*)(kg + i4);
    split_store_h(fk, (char*)(g_khi + i4), (char*)(g_klo + i4));
    float4 fv = *(const float4*)(vg + i4);
    *(__half2*)(g_vh + i4)     = __halves2half2(__float2half_rn(fv.x), __float2half_rn(fv.y));
    *(__half2*)(g_vh + i4 + 2) = __halves2half2(__float2half_rn(fv.z), __float2half_rn(fv.w));
}

__global__ void __launch_bounds__(NTH, 1)
fa_r9_kernel(const float* __restrict__ qg, const uint32_t* __restrict__ mg,
             float* __restrict__ og)
{
    extern __shared__ char smem[];
    const int tid  = threadIdx.x;
    const int lane = tid & 31;
    const int warp = tid >> 5;
    const int b    = blockIdx.y;
    const int q0   = blockIdx.x * BR;

    const float K2  = 16.3222312f;   // sqrt(128) * log2(e)
    const float NEG = -1e30f;
    const uint32_t sm0 = smem_u32(smem);

    // ---- fill helpers (cp.async) ----
    const size_t kvoff0 = (size_t)b * LK_ * DH + (size_t)(tid & 15) * 8;
    auto fill_K = [&](int kt2) {
        size_t off = kvoff0 + (size_t)kt2 * BC * DH;
        uint32_t dst0 = sm0 + (uint32_t)(SM_K + (kt2 & 1) * KSTG + (tid & 15) * 16);
        #pragma unroll
        for (int i = 0; i < 8; ++i) {
            const int p = i >> 2;
            const int row = (i & 3) * 16 + (tid >> 4);
            const __half* src = (p == 0 ? g_khi : g_klo) + off + (size_t)row * DH;
            cp16(dst0 + (uint32_t)(p * PLANE + row * RSB), src);
        }
    };
    auto fill_V = [&](int kt2) {
        size_t off = kvoff0 + (size_t)kt2 * BC * DH;
        uint32_t dst0 = sm0 + (uint32_t)(SM_V + (kt2 & 1) * PLANE + (tid & 15) * 16);
        #pragma unroll
        for (int i = 0; i < 4; ++i) {
            const int row = i * 16 + (tid >> 4);
            cp16(dst0 + (uint32_t)(row * RSB), g_vh + off + (size_t)row * DH);
        }
    };

    // start K(0)/V(0) before Q staging (overlaps LDG latency)
    fill_K(0);
    fill_V(0);
    CP_COMMIT();

    // ---- prologue: Q tile -> fp16 hi/lo persistent smem ----
    {
        const float* qp = qg + ((size_t)b * LQ_ + q0) * DH;
        #pragma unroll
        for (int i = 0; i < 16; ++i) {
            int idx = tid + i * NTH;
            int row = idx >> 5, c4 = idx & 31;
            float4 f = *(const float4*)(qp + (size_t)row * DH + c4 * 4);
            split_store_h(f, smem + SM_QHI + row * RSB + c4 * 8,
                             smem + SM_QLO + row * RSB + c4 * 8);
        }
    }

    // ---- mask prefetch (registers) ----
    const int mrow_w = warp * 16 + (lane >> 1);
    const uint32_t* mp_row = mg + (size_t)b * LQ_ * LK_ + (size_t)(q0 + mrow_w) * LK_
                                + (size_t)(lane & 1) * 32;
    uint32_t pk[8];
    auto ldgm = [&](int kt2) {
        const uint32_t* mp = mp_row + (size_t)kt2 * BC;
        #pragma unroll
        for (int j = 0; j < 8; ++j) {
            uint4 m = *(const uint4*)(mp + j * 4);
            pk[j] = (m.x ? 1u : 0u) | ((m.y ? 1u : 0u) << 8) |
                    ((m.z ? 1u : 0u) << 16) | ((m.w ? 1u : 0u) << 24);
        }
    };
    ldgm(0);

    __syncthreads();   // Q smem visible

    // qa_hi persistent in registers; qa_lo stays in smem
    uint32_t qa_hi[8][4];
    const uint32_t qfrag = sm0 + (uint32_t)((warp * 16 + (lane & 15)) * RSB + (lane >> 4) * 16);
    {
        #pragma unroll
        for (int kb = 0; kb < 8; ++kb) ldsm4(qa_hi[kb], qfrag + SM_QHI + kb * 32);
    }
    const uint32_t qlo_frag = qfrag + SM_QLO;

    float acc[16][4];
    #pragma unroll
    for (int j = 0; j < 16; ++j) { acc[j][0]=0.f; acc[j][1]=0.f; acc[j][2]=0.f; acc[j][3]=0.f; }
    float m0r = NEG, m1r = NEG, l0r = 0.f, l1r = 0.f;

    const int r0l = warp * 16 + (lane >> 2);
    const uint32_t kf_lane = (uint32_t)((lane & 7) * RSB + (lane >> 3) * 16);
    const uint32_t vf_lane = (uint32_t)((lane & 15) * RSB + (lane >> 4) * 16);
    char* mskw = smem + SM_MSK + mrow_w * MROW + (lane & 1) * 32;
    const char* mrd0 = smem + SM_MSK + r0l * MROW;
    const char* mrd1 = mrd0 + 8 * MROW;

    #pragma unroll 1
    for (int kt = 0; kt < NIT; ++kt) {
        CP_WAIT0();            // K(kt), V(kt) ready
        __syncthreads();

        if (kt + 1 < NIT) { fill_K(kt + 1); fill_V(kt + 1); }
        CP_COMMIT();

        // stage mask(kt) (warp-local rows), prefetch mask(kt+1)
        #pragma unroll
        for (int j = 0; j < 8; ++j) *(uint32_t*)(mskw + j * 4) = pk[j];
        __syncwarp();
        if (kt + 1 < NIT) ldgm(kt + 1);

        const uint32_t kfb = sm0 + (uint32_t)(SM_K + (kt & 1) * KSTG) + kf_lane;
        const uint32_t vfb = sm0 + (uint32_t)(SM_V + (kt & 1) * PLANE) + vf_lane;

        // ---- S = Q K^T (fp16 hi/lo, 3 terms; qa_lo streamed from smem) ----
        float s[8][4];
        #pragma unroll
        for (int nb = 0; nb < 8; ++nb) { s[nb][0]=0.f; s[nb][1]=0.f; s[nb][2]=0.f; s[nb][3]=0.f; }
        #pragma unroll
        for (int kp2 = 0; kp2 < 4; ++kp2) {
            const int kb0 = 2 * kp2, kb1 = 2 * kp2 + 1;
            uint32_t ql0[4], ql1[4];
            ldsm4(ql0, qlo_frag + kb0 * 32);
            ldsm4(ql1, qlo_frag + kb1 * 32);
            #pragma unroll
            for (int nbp = 0; nbp < 4; ++nbp) {
                const int n0 = 2 * nbp, n1 = 2 * nbp + 1;
                const uint32_t ka0 = kfb + (uint32_t)(n0 * 8 * RSB + kp2 * 64);
                const uint32_t ka1 = kfb + (uint32_t)(n1 * 8 * RSB + kp2 * 64);
                uint32_t bh0[4], bh1[4];
                ldsm4(bh0, ka0);
                ldsm4(bh1, ka1);
                mma_f16(s[n0], qa_hi[kb0], bh0[0], bh0[1]);
                mma_f16(s[n1], qa_hi[kb0], bh1[0], bh1[1]);
                mma_f16(s[n0], ql0,        bh0[0], bh0[1]);
                mma_f16(s[n1], ql0,        bh1[0], bh1[1]);
                mma_f16(s[n0], qa_hi[kb1], bh0[2], bh0[3]);
                mma_f16(s[n1], qa_hi[kb1], bh1[2], bh1[3]);
                mma_f16(s[n0], ql1,        bh0[2], bh0[3]);
                mma_f16(s[n1], ql1,        bh1[2], bh1[3]);
                ldsm4(bh0, ka0 + PLANE);   // reuse temps for K_lo
                ldsm4(bh1, ka1 + PLANE);
                mma_f16(s[n0], qa_hi[kb0], bh0[0], bh0[1]);
                mma_f16(s[n1], qa_hi[kb0], bh1[0], bh1[1]);
                mma_f16(s[n0], qa_hi[kb1], bh0[2], bh0[3]);
                mma_f16(s[n1], qa_hi[kb1], bh1[2], bh1[3]);
            }
        }

        // ---- mask + scale (log2 domain), online softmax ----
        float tm0 = NEG, tm1 = NEG;
        #pragma unroll
        for (int nb = 0; nb < 8; ++nb) {
            int c = (nb << 3) + ((lane & 3) << 1);
            uint32_t mm0 = *(const unsigned short*)(mrd0 + c);
            uint32_t mm1 = *(const unsigned short*)(mrd1 + c);
            s[nb][0] = (mm0 & 0xff) ? NEG : s[nb][0] * K2;
            s[nb][1] = (mm0 >> 8)   ? NEG : s[nb][1] * K2;
            s[nb][2] = (mm1 & 0xff) ? NEG : s[nb][2] * K2;
            s[nb][3] = (mm1 >> 8)   ? NEG : s[nb][3] * K2;
            tm0 = fmaxf(tm0, fmaxf(s[nb][0], s[nb][1]));
            tm1 = fmaxf(tm1, fmaxf(s[nb][2], s[nb][3]));
        }
        tm0 = fmaxf(tm0, __shfl_xor_sync(0xffffffffu, tm0, 1));
        tm0 = fmaxf(tm0, __shfl_xor_sync(0xffffffffu, tm0, 2));
        tm1 = fmaxf(tm1, __shfl_xor_sync(0xffffffffu, tm1, 1));
        tm1 = fmaxf(tm1, __shfl_xor_sync(0xffffffffu, tm1, 2));

        float mn0 = fmaxf(m0r, tm0), mn1 = fmaxf(m1r, tm1);
        float a0 = ex2f(m0r - mn0),  a1 = ex2f(m1r - mn1);
        float k0 = (mn0 > NEG) ? 1.f : 0.f;
        float k1 = (mn1 > NEG) ? 1.f : 0.f;

        float sum0 = 0.f, sum1 = 0.f;
        #pragma unroll
        for (int nb = 0; nb < 8; ++nb) {
            s[nb][0] = ex2f(s[nb][0] - mn0) * k0;
            s[nb][1] = ex2f(s[nb][1] - mn0) * k0;
            s[nb][2] = ex2f(s[nb][2] - mn1) * k1;
            s[nb][3] = ex2f(s[nb][3] - mn1) * k1;
            sum0 += s[nb][0] + s[nb][1];
            sum1 += s[nb][2] + s[nb][3];
        }
        sum0 += __shfl_xor_sync(0xffffffffu, sum0, 1);
        sum0 += __shfl_xor_sync(0xffffffffu, sum0, 2);
        sum1 += __shfl_xor_sync(0xffffffffu, sum1, 1);
        sum1 += __shfl_xor_sync(0xffffffffu, sum1, 2);
        l0r = l0r * a0 + sum0;
        l1r = l1r * a1 + sum1;
        m0r = mn0; m1r = mn1;

        if (__ballot_sync(0xffffffffu, (a0 != 1.f) || (a1 != 1.f))) {
            #pragma unroll
            for (int j = 0; j < 16; ++j) {
                acc[j][0] *= a0; acc[j][1] *= a0; acc[j][2] *= a1; acc[j][3] *= a1;
            }
        }

        // ---- O += P V (single-term fp16) ----
        #pragma unroll
        for (int kb = 0; kb < 4; ++kb) {
            uint32_t ph[4];
            ph[0] = pack_h2(s[2*kb][0],   s[2*kb][1]);
            ph[1] = pack_h2(s[2*kb][2],   s[2*kb][3]);
            ph[2] = pack_h2(s[2*kb+1][0], s[2*kb+1][1]);
            ph[3] = pack_h2(s[2*kb+1][2], s[2*kb+1][3]);
            uint32_t va = vfb + (uint32_t)(kb * 16 * RSB);
            #pragma unroll
            for (int jp = 0; jp < 8; ++jp) {
                uint32_t bh[4];
                ldsm4t(bh, va + jp * 32);
                mma_f16(acc[2*jp],   ph, bh[0], bh[1]);
                mma_f16(acc[2*jp+1], ph, bh[2], bh[3]);
            }
        }
    }

    // ---- epilogue ----
    float inv0 = (l0r > 0.f) ? (1.0f / l0r) : 0.f;
    float inv1 = (l1r > 0.f) ? (1.0f / l1r) : 0.f;
    const size_t gr0 = (size_t)b * LQ_ + q0 + r0l;
    const size_t gr1 = gr0 + 8;
    #pragma unroll
    for (int j = 0; j < 16; ++j) {
        int c = (j << 3) + ((lane & 3) << 1);
        float2 o0 = make_float2(acc[j][0] * inv0, acc[j][1] * inv0);
        float2 o1 = make_float2(acc[j][2] * inv1, acc[j][3] * inv1);
        *(float2*)(og + gr0 * DH + c) = o0;
        *(float2*)(og + gr1 * DH + c) = o1;
    }
}

} // namespace

extern "C" void kernel_launch(void* const* d_in, const int* in_sizes, int n_in,
                              void* d_out, int out_size) {
    const float* q = (const float*)d_in[0];
    const float* k = (const float*)d_in[1];
    const float* v = (const float*)d_in[2];
    const uint32_t* mask = (const uint32_t*)d_in[3];
    float* out = (float*)d_out;
    (void)in_sizes; (void)n_in; (void)out_size;

    conv_kernel<<<8192, 256>>>(k, v);

    cudaFuncSetAttribute(fa_r9_kernel, cudaFuncAttributeMaxDynamicSharedMemorySize, SM_TOT);
    dim3 grid(LQ_ / BR, B_);
    fa_r9_kernel<<<grid, NTH, SM_TOT>>>(q, mask, out);
}

// round 11
// speedup vs baseline: 1.0634x; 1.0634x over previous
#include <cuda_runtime.h>
#include <cuda_fp16.h>
#include <stdint.h>

// Flash attention, B=32, LQ=LK=2048, D=128, fp32 in/out. HMMA path.
// Mask: 4-byte elems (bool promoted); nonzero = masked. score=(q.k)*sqrt(128).
// QK^T: fp16 hi/lo 3-term MMA. PV: single-term fp16 (rel_err ~2.1e-4).
// R10: 16 warps (512 thr), 1 CTA/SM. Warp pair per 16-row group:
//   warp kh: QK/softmax on keys kh*32..+31; PV on output dims kh*64..+63.
//   Row max/sum exchanged via smem; P halves exchanged via smem tile.
// Halves the per-warp softmax chain, 4 warps/SMSP hide latency.

namespace {

constexpr int B_   = 32;
constexpr int LQ_  = 2048;
constexpr int LK_  = 2048;
constexpr int DH   = 128;
constexpr int BR   = 128;
constexpr int BC   = 64;
constexpr int NTH  = 512;   // 16 warps
constexpr int NIT  = LK_ / BC;
constexpr int RSB  = 272;   // 128 fp16 + 16B pad

constexpr int PLANE  = BC * RSB;        // 17408
constexpr int QPLANE = BR * RSB;        // 34816
constexpr int KSTG   = 2 * PLANE;       // K hi+lo stage

constexpr int SM_QHI = 0;                       // persistent Q hi
constexpr int SM_QLO = QPLANE;                  // persistent Q lo
constexpr int SM_K   = 2 * QPLANE;              // 2 K stages
constexpr int SM_V   = SM_K + 2 * KSTG;         // 2 V planes
constexpr int SM_P   = SM_V + 2 * PLANE;        // P exchange tile, 128 x 64 fp16
constexpr int PRSB   = 144;                     // 64 fp16 + 16B pad
constexpr int SM_MAX = SM_P + BR * PRSB;        // partial max: [8 rg][2 kh][16]
constexpr int SM_SUM = SM_MAX + 1024;           // partial sum: same shape
constexpr int SM_MSK = SM_SUM + 1024;           // per-warp mask: 16 x 576
constexpr int MROW2  = 36;
constexpr int SM_TOT = SM_MSK + 16 * 16 * MROW2;  // 203776 B

__device__ __half g_khi[(size_t)B_ * LK_ * DH];
__device__ __half g_klo[(size_t)B_ * LK_ * DH];
__device__ __half g_vh [(size_t)B_ * LK_ * DH];

__device__ __forceinline__ uint32_t smem_u32(const void* p) {
    return (uint32_t)__cvta_generic_to_shared(p);
}
__device__ __forceinline__ void cp16(uint32_t dst, const void* src) {
    asm volatile("cp.async.cg.shared.global [%0], [%1], 16;" :: "r"(dst), "l"(src));
}
#define CP_COMMIT() asm volatile("cp.async.commit_group;")
#define CP_WAIT0()  asm volatile("cp.async.wait_group 0;")

__device__ __forceinline__ void ldsm4(uint32_t r[4], uint32_t a) {
    asm volatile("ldmatrix.sync.aligned.m8n8.x4.shared.b16 {%0,%1,%2,%3}, [%4];"
                 : "=r"(r[0]), "=r"(r[1]), "=r"(r[2]), "=r"(r[3]) : "r"(a));
}
__device__ __forceinline__ void ldsm4t(uint32_t r[4], uint32_t a) {
    asm volatile("ldmatrix.sync.aligned.m8n8.x4.trans.shared.b16 {%0,%1,%2,%3}, [%4];"
                 : "=r"(r[0]), "=r"(r[1]), "=r"(r[2]), "=r"(r[3]) : "r"(a));
}
__device__ __forceinline__ void mma_f16(float d[4], const uint32_t a[4], uint32_t b0, uint32_t b1) {
    asm volatile("mma.sync.aligned.m16n8k16.row.col.f32.f16.f16.f32 "
                 "{%0,%1,%2,%3}, {%4,%5,%6,%7}, {%8,%9}, {%0,%1,%2,%3};"
                 : "+f"(d[0]), "+f"(d[1]), "+f"(d[2]), "+f"(d[3])
                 : "r"(a[0]), "r"(a[1]), "r"(a[2]), "r"(a[3]), "r"(b0), "r"(b1));
}
__device__ __forceinline__ float ex2f(float x) {
    float y; asm("ex2.approx.f32 %0, %1;" : "=f"(y) : "f"(x)); return y;
}
__device__ __forceinline__ uint32_t bits2h(__half2 h) {
    uint32_t u; __builtin_memcpy(&u, &h, 4); return u;
}
__device__ __forceinline__ void split_store_h(float4 f, char* ph, char* pl) {
    __half h0 = __float2half_rn(f.x);
    __half h1 = __float2half_rn(f.y);
    __half h2 = __float2half_rn(f.z);
    __half h3 = __float2half_rn(f.w);
    *(__half2*)(ph)     = __halves2half2(h0, h1);
    *(__half2*)(ph + 4) = __halves2half2(h2, h3);
    __half l0 = __float2half_rn(f.x - __half2float(h0));
    __half l1 = __float2half_rn(f.y - __half2float(h1));
    __half l2 = __float2half_rn(f.z - __half2float(h2));
    __half l3 = __float2half_rn(f.w - __half2float(h3));
    *(__half2*)(pl)     = __halves2half2(l0, l1);
    *(__half2*)(pl + 4) = __halves2half2(l2, l3);
}
__device__ __forceinline__ uint32_t pack_h2(float x, float y) {
    return bits2h(__halves2half2(__float2half_rn(x), __float2half_rn(y)));
}

__global__ void __launch_bounds__(256, 4)
conv_kernel(const float* __restrict__ kg, const float* __restrict__ vg)
{
    size_t i4 = ((size_t)blockIdx.x * 256 + threadIdx.x) * 4;
    float4 fk = *(const float4*)(kg + i4);
    split_store_h(fk, (char*)(g_khi + i4), (char*)(g_klo + i4));
    float4 fv = *(const float4*)(vg + i4);
    *(__half2*)(g_vh + i4)     = __halves2half2(__float2half_rn(fv.x), __float2half_rn(fv.y));
    *(__half2*)(g_vh + i4 + 2) = __halves2half2(__float2half_rn(fv.z), __float2half_rn(fv.w));
}

__global__ void __launch_bounds__(NTH, 1)
fa_r10_kernel(const float* __restrict__ qg, const uint32_t* __restrict__ mg,
              float* __restrict__ og)
{
    extern __shared__ char smem[];
    const int tid  = threadIdx.x;
    const int lane = tid & 31;
    const int warp = tid >> 5;
    const int rg   = warp >> 1;      // row group 0..7 (rows rg*16..+15)
    const int kh   = warp & 1;       // key half (QK) / dim half (PV)
    const int R0   = rg * 16;
    const int b    = blockIdx.y;
    const int q0   = blockIdx.x * BR;

    const float K2  = 16.3222312f;   // sqrt(128) * log2(e)
    const float NEG = -1e30f;
    const uint32_t sm0 = smem_u32(smem);

    // ---- fill helpers ----
    const size_t kvoff0 = (size_t)b * LK_ * DH;
    auto fill_K = [&](int kt2) {
        size_t off = kvoff0 + (size_t)kt2 * BC * DH;
        uint32_t dst0 = sm0 + (uint32_t)(SM_K + (kt2 & 1) * KSTG);
        #pragma unroll
        for (int i = 0; i < 4; ++i) {
            int idx = tid + i * NTH;              // 0..2047
            int p = idx >> 10, r = (idx >> 4) & 63, c = idx & 15;
            const __half* src = (p == 0 ? g_khi : g_klo) + off + (size_t)r * DH + c * 8;
            cp16(dst0 + (uint32_t)(p * PLANE + r * RSB + c * 16), src);
        }
    };
    auto fill_V = [&](int kt2) {
        size_t off = kvoff0 + (size_t)kt2 * BC * DH;
        uint32_t dst0 = sm0 + (uint32_t)(SM_V + (kt2 & 1) * PLANE);
        #pragma unroll
        for (int i = 0; i < 2; ++i) {
            int idx = tid + i * NTH;              // 0..1023
            int r = (idx >> 4) & 63, c = idx & 15;
            cp16(dst0 + (uint32_t)(r * RSB + c * 16), g_vh + off + (size_t)r * DH + c * 8);
        }
    };

    fill_K(0);
    fill_V(0);
    CP_COMMIT();

    // ---- Q tile -> fp16 hi/lo persistent smem ----
    {
        const float* qp = qg + ((size_t)b * LQ_ + q0) * DH;
        #pragma unroll
        for (int i = 0; i < 8; ++i) {
            int idx = tid + i * NTH;              // 4096 float4
            int row = idx >> 5, c4 = idx & 31;
            float4 f = *(const float4*)(qp + (size_t)row * DH + c4 * 4);
            split_store_h(f, smem + SM_QHI + row * RSB + c4 * 8,
                             smem + SM_QLO + row * RSB + c4 * 8);
        }
    }

    // ---- mask prefetch: rows R0+ (lane>>1), keys kh*32 + (lane&1)*16 + 0..15 ----
    const int mrow_m = lane >> 1;
    const int mhalf  = lane & 1;
    const uint32_t* mp_row = mg + (size_t)b * LQ_ * LK_
                           + (size_t)(q0 + R0 + mrow_m) * LK_ + kh * 32 + mhalf * 16;
    uint32_t pk[4];
    auto ldgm = [&](int kt2) {
        const uint32_t* mp = mp_row + (size_t)kt2 * BC;
        #pragma unroll
        for (int j = 0; j < 4; ++j) {
            uint4 m = *(const uint4*)(mp + j * 4);
            pk[j] = (m.x ? 1u : 0u) | ((m.y ? 1u : 0u) << 8) |
                    ((m.z ? 1u : 0u) << 16) | ((m.w ? 1u : 0u) << 24);
        }
    };
    ldgm(0);
    __syncthreads();   // Q visible

    float acc[8][4];   // 16 rows x 64 dims (this warp's D-half)
    #pragma unroll
    for (int j = 0; j < 8; ++j) { acc[j][0]=0.f; acc[j][1]=0.f; acc[j][2]=0.f; acc[j][3]=0.f; }
    float m0r = NEG, m1r = NEG, l0r = 0.f, l1r = 0.f;

    const int r0q = lane >> 2;          // local row (C-frag); +8 for second half
    const uint32_t qfrag  = sm0 + (uint32_t)((R0 + (lane & 15)) * RSB + (lane >> 4) * 16);
    const uint32_t kf_l   = sm0 + (uint32_t)(SM_K) + (uint32_t)((lane & 7) * RSB + (lane >> 3) * 16 + kh * 32 * RSB);
    const uint32_t pfrag  = sm0 + (uint32_t)(SM_P + (R0 + (lane & 15)) * PRSB + (lane >> 4) * 16);
    const uint32_t pwr0   = sm0 + (uint32_t)(SM_P + (R0 + r0q) * PRSB + kh * 64 + ((lane & 3) << 2));
    const uint32_t vf_l   = sm0 + (uint32_t)(SM_V) + (uint32_t)((lane & 15) * RSB + (lane >> 4) * 16 + kh * 128);
    char* mskw = smem + SM_MSK + warp * (16 * MROW2) + mrow_m * MROW2 + mhalf * 16;
    const char* mrd0 = smem + SM_MSK + warp * (16 * MROW2) + r0q * MROW2;
    const char* mrd1 = mrd0 + 8 * MROW2;
    // partial max/sum buffers: [rg][kh][16]
    float* maxme = (float*)(smem + SM_MAX) + (rg * 2 + kh) * 16;
    float* maxpr = (float*)(smem + SM_MAX) + (rg * 2 + (kh ^ 1)) * 16;
    float* summe = (float*)(smem + SM_SUM) + (rg * 2 + kh) * 16;
    float* sumpr = (float*)(smem + SM_SUM) + (rg * 2 + (kh ^ 1)) * 16;

    #pragma unroll 1
    for (int kt = 0; kt < NIT; ++kt) {
        CP_WAIT0();
        __syncthreads();                       // K/V(kt) ready; prev P consumed

        if (kt + 1 < NIT) { fill_K(kt + 1); fill_V(kt + 1); }
        CP_COMMIT();

        // stage mask(kt) (warp-local), prefetch mask(kt+1)
        #pragma unroll
        for (int j = 0; j < 4; ++j) *(uint32_t*)(mskw + j * 4) = pk[j];
        __syncwarp();
        if (kt + 1 < NIT) ldgm(kt + 1);

        const uint32_t kfb = kf_l + (uint32_t)((kt & 1) * KSTG);

        // ---- S = Q K^T : 16 rows x 32 keys, fp16 hi/lo 3 terms ----
        float s[4][4];
        #pragma unroll
        for (int nb = 0; nb < 4; ++nb) { s[nb][0]=0.f; s[nb][1]=0.f; s[nb][2]=0.f; s[nb][3]=0.f; }
        #pragma unroll
        for (int kp2 = 0; kp2 < 4; ++kp2) {
            uint32_t qh0[4], qh1[4], ql0[4], ql1[4];
            ldsm4(qh0, qfrag + SM_QHI + (2 * kp2)     * 32);
            ldsm4(qh1, qfrag + SM_QHI + (2 * kp2 + 1) * 32);
            ldsm4(ql0, qfrag + SM_QLO + (2 * kp2)     * 32);
            ldsm4(ql1, qfrag + SM_QLO + (2 * kp2 + 1) * 32);
            #pragma unroll
            for (int nbp = 0; nbp < 2; ++nbp) {
                const int n0 = 2 * nbp, n1 = 2 * nbp + 1;
                const uint32_t ka0 = kfb + (uint32_t)(n0 * 8 * RSB + kp2 * 64);
                const uint32_t ka1 = kfb + (uint32_t)(n1 * 8 * RSB + kp2 * 64);
                uint32_t bh0[4], bh1[4];
                ldsm4(bh0, ka0);
                ldsm4(bh1, ka1);
                mma_f16(s[n0], qh0, bh0[0], bh0[1]);
                mma_f16(s[n1], qh0, bh1[0], bh1[1]);
                mma_f16(s[n0], ql0, bh0[0], bh0[1]);
                mma_f16(s[n1], ql0, bh1[0], bh1[1]);
                mma_f16(s[n0], qh1, bh0[2], bh0[3]);
                mma_f16(s[n1], qh1, bh1[2], bh1[3]);
                mma_f16(s[n0], ql1, bh0[2], bh0[3]);
                mma_f16(s[n1], ql1, bh1[2], bh1[3]);
                ldsm4(bh0, ka0 + PLANE);       // K lo
                ldsm4(bh1, ka1 + PLANE);
                mma_f16(s[n0], qh0, bh0[0], bh0[1]);
                mma_f16(s[n1], qh0, bh1[0], bh1[1]);
                mma_f16(s[n0], qh1, bh0[2], bh0[3]);
                mma_f16(s[n1], qh1, bh1[2], bh1[3]);
            }
        }

        // ---- mask + scale, partial row max over this key half ----
        float tm0 = NEG, tm1 = NEG;
        #pragma unroll
        for (int nb = 0; nb < 4; ++nb) {
            int c = (nb << 3) + ((lane & 3) << 1);
            uint32_t mm0 = *(const unsigned short*)(mrd0 + c);
            uint32_t mm1 = *(const unsigned short*)(mrd1 + c);
            s[nb][0] = (mm0 & 0xff) ? NEG : s[nb][0] * K2;
            s[nb][1] = (mm0 >> 8)   ? NEG : s[nb][1] * K2;
            s[nb][2] = (mm1 & 0xff) ? NEG : s[nb][2] * K2;
            s[nb][3] = (mm1 >> 8)   ? NEG : s[nb][3] * K2;
            tm0 = fmaxf(tm0, fmaxf(s[nb][0], s[nb][1]));
            tm1 = fmaxf(tm1, fmaxf(s[nb][2], s[nb][3]));
        }
        tm0 = fmaxf(tm0, __shfl_xor_sync(0xffffffffu, tm0, 1));
        tm0 = fmaxf(tm0, __shfl_xor_sync(0xffffffffu, tm0, 2));
        tm1 = fmaxf(tm1, __shfl_xor_sync(0xffffffffu, tm1, 1));
        tm1 = fmaxf(tm1, __shfl_xor_sync(0xffffffffu, tm1, 2));
        if ((lane & 3) == 0) { maxme[r0q] = tm0; maxme[r0q + 8] = tm1; }
        __syncthreads();                       // max exchange
        tm0 = fmaxf(tm0, maxpr[r0q]);
        tm1 = fmaxf(tm1, maxpr[r0q + 8]);

        float mn0 = fmaxf(m0r, tm0), mn1 = fmaxf(m1r, tm1);
        float a0 = ex2f(m0r - mn0),  a1 = ex2f(m1r - mn1);
        float k0 = (mn0 > NEG) ? 1.f : 0.f;
        float k1 = (mn1 > NEG) ? 1.f : 0.f;

        float sum0 = 0.f, sum1 = 0.f;
        #pragma unroll
        for (int nb = 0; nb < 4; ++nb) {
            s[nb][0] = ex2f(s[nb][0] - mn0) * k0;
            s[nb][1] = ex2f(s[nb][1] - mn0) * k0;
            s[nb][2] = ex2f(s[nb][2] - mn1) * k1;
            s[nb][3] = ex2f(s[nb][3] - mn1) * k1;
            sum0 += s[nb][0] + s[nb][1];
            sum1 += s[nb][2] + s[nb][3];
        }
        sum0 += __shfl_xor_sync(0xffffffffu, sum0, 1);
        sum0 += __shfl_xor_sync(0xffffffffu, sum0, 2);
        sum1 += __shfl_xor_sync(0xffffffffu, sum1, 1);
        sum1 += __shfl_xor_sync(0xffffffffu, sum1, 2);
        if ((lane & 3) == 0) { summe[r0q] = sum0; summe[r0q + 8] = sum1; }

        // write P half (fp16) for partner: [row, kh*32 + c]
        #pragma unroll
        for (int nb = 0; nb < 4; ++nb) {
            uint32_t p0 = pack_h2(s[nb][0], s[nb][1]);
            uint32_t p1 = pack_h2(s[nb][2], s[nb][3]);
            uint32_t a_ = pwr0 + (uint32_t)(nb * 16);
            asm volatile("st.shared.b32 [%0], %1;" :: "r"(a_), "r"(p0));
            asm volatile("st.shared.b32 [%0], %1;" :: "r"(a_ + 8 * PRSB), "r"(p1));
        }
        __syncthreads();                       // sum + P exchange

        sum0 += sumpr[r0q];
        sum1 += sumpr[r0q + 8];
        l0r = l0r * a0 + sum0;
        l1r = l1r * a1 + sum1;
        m0r = mn0; m1r = mn1;

        if (__ballot_sync(0xffffffffu, (a0 != 1.f) || (a1 != 1.f))) {
            #pragma unroll
            for (int j = 0; j < 8; ++j) {
                acc[j][0] *= a0; acc[j][1] *= a0; acc[j][2] *= a1; acc[j][3] *= a1;
            }
        }

        // ---- O(half D) += P(16x64 full keys) V : single-term fp16 ----
        const uint32_t vfb = vf_l + (uint32_t)((kt & 1) * PLANE);
        #pragma unroll
        for (int kb = 0; kb < 4; ++kb) {
            uint32_t pa[4];
            ldsm4(pa, pfrag + kb * 32);
            uint32_t va = vfb + (uint32_t)(kb * 16 * RSB);
            #pragma unroll
            for (int jp = 0; jp < 4; ++jp) {
                uint32_t bv[4];
                ldsm4t(bv, va + jp * 32);
                mma_f16(acc[2*jp],   pa, bv[0], bv[1]);
                mma_f16(acc[2*jp+1], pa, bv[2], bv[3]);
            }
        }
    }

    // ---- epilogue: rows R0+r0q / +8, dims kh*64 + ... ----
    float inv0 = (l0r > 0.f) ? (1.0f / l0r) : 0.f;
    float inv1 = (l1r > 0.f) ? (1.0f / l1r) : 0.f;
    const size_t gr0 = (size_t)b * LQ_ + q0 + R0 + r0q;
    const size_t gr1 = gr0 + 8;
    #pragma unroll
    for (int j = 0; j < 8; ++j) {
        int col = kh * 64 + (j >> 1) * 16 + (j & 1) * 8 + ((lane & 3) << 1);
        float2 o0 = make_float2(acc[j][0] * inv0, acc[j][1] * inv0);
        float2 o1 = make_float2(acc[j][2] * inv1, acc[j][3] * inv1);
        *(float2*)(og + gr0 * DH + col) = o0;
        *(float2*)(og + gr1 * DH + col) = o1;
    }
}

} // namespace

extern "C" void kernel_launch(void* const* d_in, const int* in_sizes, int n_in,
                              void* d_out, int out_size) {
    const float* q = (const float*)d_in[0];
    const float* k = (const float*)d_in[1];
    const float* v = (const float*)d_in[2];
    const uint32_t* mask = (const uint32_t*)d_in[3];
    float* out = (float*)d_out;
    (void)in_sizes; (void)n_in; (void)out_size;

    conv_kernel<<<8192, 256>>>(k, v);

    cudaFuncSetAttribute(fa_r10_kernel, cudaFuncAttributeMaxDynamicSharedMemorySize, SM_TOT);
    dim3 grid(LQ_ / BR, B_);
    fa_r10_kernel<<<grid, NTH, SM_TOT>>>(q, mask, out);
}

// round 12
// speedup vs baseline: 1.0795x; 1.0152x over previous
#include <cuda_runtime.h>
#include <cuda_fp16.h>
#include <stdint.h>

// Flash attention, B=32, LQ=LK=2048, D=128, fp32 in/out. HMMA path.
// Mask: 4-byte elems (bool promoted); nonzero = masked. score=(q.k)*sqrt(128).
// QK^T: fp16 hi/lo 3-term MMA. PV: single-term fp16 (rel_err ~2.1e-4).
// R11: softmax(kt-1) is sliced into 16 chunks and fused between the 16 QK(kt)
// MMA-issue steps. mma.sync issue is backpressure-throttled, so ALU chunks
// fill the stall slots -> tensor pipe stays busy during softmax.

namespace {

constexpr int B_   = 32;
constexpr int LQ_  = 2048;
constexpr int LK_  = 2048;
constexpr int DH   = 128;
constexpr int BR   = 128;
constexpr int BC   = 64;
constexpr int NTH  = 256;
constexpr int NIT  = LK_ / BC;
constexpr int RSB  = 272;             // 128 fp16 + 16B pad

constexpr int PLANE = BC * RSB;       // 17408 B
constexpr int KSTG  = 2 * PLANE;      // K hi+lo stage
constexpr int SM_K  = 0;              // 2 stages: 69632
constexpr int SM_V  = 2 * KSTG;       // V: 3 stages x 1 fp16 plane
constexpr int SM_MSK = SM_V + 3 * PLANE;
constexpr int MROW  = 68;
constexpr int MSKSTG = BR * MROW;     // x2 stages
constexpr int SM_TOT = SM_MSK + 2 * MSKSTG;   // 139264 B

constexpr int SM_QHI = 0;             // prologue overlay on K region
constexpr int SM_QLO = BR * RSB;

__device__ __half g_khi[(size_t)B_ * LK_ * DH];
__device__ __half g_klo[(size_t)B_ * LK_ * DH];
__device__ __half g_vh [(size_t)B_ * LK_ * DH];

__device__ __forceinline__ uint32_t smem_u32(const void* p) {
    return (uint32_t)__cvta_generic_to_shared(p);
}
__device__ __forceinline__ void cp16(uint32_t dst, const void* src) {
    asm volatile("cp.async.cg.shared.global [%0], [%1], 16;" :: "r"(dst), "l"(src));
}
#define CP_COMMIT() asm volatile("cp.async.commit_group;")
#define CP_WAIT0()  asm volatile("cp.async.wait_group 0;")

__device__ __forceinline__ void ldsm4(uint32_t r[4], uint32_t a) {
    asm volatile("ldmatrix.sync.aligned.m8n8.x4.shared.b16 {%0,%1,%2,%3}, [%4];"
                 : "=r"(r[0]), "=r"(r[1]), "=r"(r[2]), "=r"(r[3]) : "r"(a));
}
__device__ __forceinline__ void ldsm4t(uint32_t r[4], uint32_t a) {
    asm volatile("ldmatrix.sync.aligned.m8n8.x4.trans.shared.b16 {%0,%1,%2,%3}, [%4];"
                 : "=r"(r[0]), "=r"(r[1]), "=r"(r[2]), "=r"(r[3]) : "r"(a));
}
__device__ __forceinline__ void mma_f16(float d[4], const uint32_t a[4], uint32_t b0, uint32_t b1) {
    asm volatile("mma.sync.aligned.m16n8k16.row.col.f32.f16.f16.f32 "
                 "{%0,%1,%2,%3}, {%4,%5,%6,%7}, {%8,%9}, {%0,%1,%2,%3};"
                 : "+f"(d[0]), "+f"(d[1]), "+f"(d[2]), "+f"(d[3])
                 : "r"(a[0]), "r"(a[1]), "r"(a[2]), "r"(a[3]), "r"(b0), "r"(b1));
}
__device__ __forceinline__ float ex2f(float x) {
    float y; asm("ex2.approx.f32 %0, %1;" : "=f"(y) : "f"(x)); return y;
}
__device__ __forceinline__ uint32_t bits2h(__half2 h) {
    uint32_t u; __builtin_memcpy(&u, &h, 4); return u;
}
__device__ __forceinline__ void split_store_h(float4 f, char* ph, char* pl) {
    __half h0 = __float2half_rn(f.x);
    __half h1 = __float2half_rn(f.y);
    __half h2 = __float2half_rn(f.z);
    __half h3 = __float2half_rn(f.w);
    *(__half2*)(ph)     = __halves2half2(h0, h1);
    *(__half2*)(ph + 4) = __halves2half2(h2, h3);
    __half l0 = __float2half_rn(f.x - __half2float(h0));
    __half l1 = __float2half_rn(f.y - __half2float(h1));
    __half l2 = __float2half_rn(f.z - __half2float(h2));
    __half l3 = __float2half_rn(f.w - __half2float(h3));
    *(__half2*)(pl)     = __halves2half2(l0, l1);
    *(__half2*)(pl + 4) = __halves2half2(l2, l3);
}
__device__ __forceinline__ uint32_t pack_h2(float x, float y) {
    return bits2h(__halves2half2(__float2half_rn(x), __float2half_rn(y)));
}

__global__ void __launch_bounds__(256, 4)
conv_kernel(const float* __restrict__ kg, const float* __restrict__ vg)
{
    size_t i4 = ((size_t)blockIdx.x * 256 + threadIdx.x) * 4;
    float4 fk = *(const float4*)(kg + i4);
    split_store_h(fk, (char*)(g_khi + i4), (char*)(g_klo + i4));
    float4 fv = *(const float4*)(vg + i4);
    *(__half2*)(g_vh + i4)     = __halves2half2(__float2half_rn(fv.x), __float2half_rn(fv.y));
    *(__half2*)(g_vh + i4 + 2) = __halves2half2(__float2half_rn(fv.z), __float2half_rn(fv.w));
}

__global__ void __launch_bounds__(NTH, 1)
fa_r11_kernel(const float* __restrict__ qg, const uint32_t* __restrict__ mg,
              float* __restrict__ og)
{
    extern __shared__ char smem[];
    const int tid  = threadIdx.x;
    const int lane = tid & 31;
    const int warp = tid >> 5;
    const int b    = blockIdx.y;
    const int q0   = blockIdx.x * BR;

    const float K2  = 16.3222312f;   // sqrt(128) * log2(e)
    const float NEG = -1e30f;
    const uint32_t sm0 = smem_u32(smem);

    // ---- prologue: Q tile -> fp16 hi/lo smem (overlays K buffers) ----
    {
        const float* qp = qg + ((size_t)b * LQ_ + q0) * DH;
        #pragma unroll
        for (int i = 0; i < 16; ++i) {
            int idx = tid + i * NTH;
            int row = idx >> 5, c4 = idx & 31;
            float4 f = *(const float4*)(qp + (size_t)row * DH + c4 * 4);
            split_store_h(f, smem + SM_QHI + row * RSB + c4 * 8,
                             smem + SM_QLO + row * RSB + c4 * 8);
        }
    }
    __syncthreads();

    uint32_t qa_hi[8][4], qa_lo[8][4];
    {
        uint32_t base = sm0 + (uint32_t)((warp * 16 + (lane & 15)) * RSB + (lane >> 4) * 16);
        #pragma unroll
        for (int kb = 0; kb < 8; ++kb) {
            ldsm4(qa_hi[kb], base + SM_QHI + kb * 32);
            ldsm4(qa_lo[kb], base + SM_QLO + kb * 32);
        }
    }
    __syncthreads();

    // ---- fill helpers ----
    const size_t kvoff0 = (size_t)b * LK_ * DH + (size_t)(tid & 15) * 8;
    auto fill_K = [&](int kt2) {
        size_t off = kvoff0 + (size_t)kt2 * BC * DH;
        uint32_t dst0 = sm0 + (uint32_t)(SM_K + (kt2 & 1) * KSTG + (tid & 15) * 16);
        #pragma unroll
        for (int i = 0; i < 8; ++i) {
            const int p = i >> 2;
            const int row = (i & 3) * 16 + (tid >> 4);
            const __half* src = (p == 0 ? g_khi : g_klo) + off + (size_t)row * DH;
            cp16(dst0 + (uint32_t)(p * PLANE + row * RSB), src);
        }
    };
    auto fill_V = [&](int kt2, int vst) {
        size_t off = kvoff0 + (size_t)kt2 * BC * DH;
        uint32_t dst0 = sm0 + (uint32_t)(SM_V + vst * PLANE + (tid & 15) * 16);
        #pragma unroll
        for (int i = 0; i < 4; ++i) {
            const int row = i * 16 + (tid >> 4);
            cp16(dst0 + (uint32_t)(row * RSB), g_vh + off + (size_t)row * DH);
        }
    };

    // ---- mask prefetch + warp-local smem stage ----
    const int mrow_w = warp * 16 + (lane >> 1);
    const uint32_t* mp_row = mg + (size_t)b * LQ_ * LK_ + (size_t)(q0 + mrow_w) * LK_
                                + (size_t)(lane & 1) * 32;
    uint32_t pk[8];
    auto ldgm = [&](int kt2) {
        const uint32_t* mp = mp_row + (size_t)kt2 * BC;
        #pragma unroll
        for (int j = 0; j < 8; ++j) {
            uint4 m = *(const uint4*)(mp + j * 4);
            pk[j] = (m.x ? 1u : 0u) | ((m.y ? 1u : 0u) << 8) |
                    ((m.z ? 1u : 0u) << 16) | ((m.w ? 1u : 0u) << 24);
        }
    };

    fill_K(0);
    fill_V(0, 0);
    CP_COMMIT();
    ldgm(0);

    float acc[16][4];
    #pragma unroll
    for (int j = 0; j < 16; ++j) { acc[j][0]=0.f; acc[j][1]=0.f; acc[j][2]=0.f; acc[j][3]=0.f; }
    float m0r = NEG, m1r = NEG, l0r = 0.f, l1r = 0.f;

    const int r0l = warp * 16 + (lane >> 2);
    const uint32_t kf_lane = (uint32_t)((lane & 7) * RSB + (lane >> 3) * 16);
    const uint32_t vf_lane = (uint32_t)((lane & 15) * RSB + (lane >> 4) * 16);
    char* mskw0 = smem + SM_MSK + mrow_w * MROW + (lane & 1) * 32;
    const char* mrd_base = smem + SM_MSK + r0l * MROW;

    float sA[8][4], sB[8][4];

    // ---- plain QK (kt = 0 only) ----
    auto qk_plain = [&](int kt, float (&sC)[8][4]) {
        const uint32_t kfb = sm0 + (uint32_t)(SM_K + (kt & 1) * KSTG) + kf_lane;
        #pragma unroll
        for (int nb = 0; nb < 8; ++nb) { sC[nb][0]=0.f; sC[nb][1]=0.f; sC[nb][2]=0.f; sC[nb][3]=0.f; }
        #pragma unroll
        for (int kp2 = 0; kp2 < 4; ++kp2) {
            const int kb0 = 2 * kp2, kb1 = 2 * kp2 + 1;
            #pragma unroll
            for (int nbp = 0; nbp < 4; ++nbp) {
                const int n0 = 2 * nbp, n1 = 2 * nbp + 1;
                const uint32_t ka0 = kfb + (uint32_t)(n0 * 8 * RSB + kp2 * 64);
                const uint32_t ka1 = kfb + (uint32_t)(n1 * 8 * RSB + kp2 * 64);
                uint32_t bh0[4], bh1[4];
                ldsm4(bh0, ka0);
                ldsm4(bh1, ka1);
                mma_f16(sC[n0], qa_hi[kb0], bh0[0], bh0[1]);
                mma_f16(sC[n1], qa_hi[kb0], bh1[0], bh1[1]);
                mma_f16(sC[n0], qa_lo[kb0], bh0[0], bh0[1]);
                mma_f16(sC[n1], qa_lo[kb0], bh1[0], bh1[1]);
                mma_f16(sC[n0], qa_hi[kb1], bh0[2], bh0[3]);
                mma_f16(sC[n1], qa_hi[kb1], bh1[2], bh1[3]);
                mma_f16(sC[n0], qa_lo[kb1], bh0[2], bh0[3]);
                mma_f16(sC[n1], qa_lo[kb1], bh1[2], bh1[3]);
                ldsm4(bh0, ka0 + PLANE);
                ldsm4(bh1, ka1 + PLANE);
                mma_f16(sC[n0], qa_hi[kb0], bh0[0], bh0[1]);
                mma_f16(sC[n1], qa_hi[kb0], bh1[0], bh1[1]);
                mma_f16(sC[n0], qa_hi[kb1], bh0[2], bh0[3]);
                mma_f16(sC[n1], qa_hi[kb1], bh1[2], bh1[3]);
            }
        }
    };

    // ---- fused: QK(kt) with softmax(kt-1) chunks interleaved ----
    auto fused = [&](int kt, float (&sC)[8][4], float (&s)[8][4]) {
        const uint32_t kfb = sm0 + (uint32_t)(SM_K + (kt & 1) * KSTG) + kf_lane;
        const char* mrd0 = mrd_base + ((kt - 1) & 1) * MSKSTG;
        const char* mrd1 = mrd0 + 8 * MROW;
        #pragma unroll
        for (int nb = 0; nb < 8; ++nb) { sC[nb][0]=0.f; sC[nb][1]=0.f; sC[nb][2]=0.f; sC[nb][3]=0.f; }
        float tm0 = NEG, tm1 = NEG;
        float mn0 = 0.f, mn1 = 0.f, a0 = 1.f, a1 = 1.f, k0 = 1.f, k1 = 1.f;
        float sum0 = 0.f, sum1 = 0.f;

        #pragma unroll
        for (int kp2 = 0; kp2 < 4; ++kp2) {
            const int kb0 = 2 * kp2, kb1 = 2 * kp2 + 1;
            #pragma unroll
            for (int nbp = 0; nbp < 4; ++nbp) {
                const int u  = kp2 * 4 + nbp;
                const int n0 = 2 * nbp, n1 = 2 * nbp + 1;
                const uint32_t ka0 = kfb + (uint32_t)(n0 * 8 * RSB + kp2 * 64);
                const uint32_t ka1 = kfb + (uint32_t)(n1 * 8 * RSB + kp2 * 64);
                uint32_t bh0[4], bh1[4];
                ldsm4(bh0, ka0);
                ldsm4(bh1, ka1);
                mma_f16(sC[n0], qa_hi[kb0], bh0[0], bh0[1]);
                mma_f16(sC[n1], qa_hi[kb0], bh1[0], bh1[1]);
                mma_f16(sC[n0], qa_lo[kb0], bh0[0], bh0[1]);
                mma_f16(sC[n1], qa_lo[kb0], bh1[0], bh1[1]);
                mma_f16(sC[n0], qa_hi[kb1], bh0[2], bh0[3]);
                mma_f16(sC[n1], qa_hi[kb1], bh1[2], bh1[3]);
                mma_f16(sC[n0], qa_lo[kb1], bh0[2], bh0[3]);
                mma_f16(sC[n1], qa_lo[kb1], bh1[2], bh1[3]);

                // -------- softmax(kt-1) chunk u (fills MMA backpressure) ----
                if (u < 8) {
                    const int nb = u;
                    int c = (nb << 3) + ((lane & 3) << 1);
                    uint32_t mm0 = *(const unsigned short*)(mrd0 + c);
                    uint32_t mm1 = *(const unsigned short*)(mrd1 + c);
                    s[nb][0] = (mm0 & 0xff) ? NEG : s[nb][0] * K2;
                    s[nb][1] = (mm0 >> 8)   ? NEG : s[nb][1] * K2;
                    s[nb][2] = (mm1 & 0xff) ? NEG : s[nb][2] * K2;
                    s[nb][3] = (mm1 >> 8)   ? NEG : s[nb][3] * K2;
                    tm0 = fmaxf(tm0, fmaxf(s[nb][0], s[nb][1]));
                    tm1 = fmaxf(tm1, fmaxf(s[nb][2], s[nb][3]));
                } else if (u == 8) {
                    tm0 = fmaxf(tm0, __shfl_xor_sync(0xffffffffu, tm0, 1));
                    tm0 = fmaxf(tm0, __shfl_xor_sync(0xffffffffu, tm0, 2));
                    tm1 = fmaxf(tm1, __shfl_xor_sync(0xffffffffu, tm1, 1));
                    tm1 = fmaxf(tm1, __shfl_xor_sync(0xffffffffu, tm1, 2));
                    mn0 = fmaxf(m0r, tm0); mn1 = fmaxf(m1r, tm1);
                    a0 = ex2f(m0r - mn0);  a1 = ex2f(m1r - mn1);
                    k0 = (mn0 > NEG) ? 1.f : 0.f;
                    k1 = (mn1 > NEG) ? 1.f : 0.f;
                    m0r = mn0; m1r = mn1;
                } else if (u <= 12) {
                    #pragma unroll
                    for (int q2 = 0; q2 < 2; ++q2) {
                        const int nb = 2 * (u - 9) + q2;
                        s[nb][0] = ex2f(s[nb][0] - mn0) * k0;
                        s[nb][1] = ex2f(s[nb][1] - mn0) * k0;
                        s[nb][2] = ex2f(s[nb][2] - mn1) * k1;
                        s[nb][3] = ex2f(s[nb][3] - mn1) * k1;
                        sum0 += s[nb][0] + s[nb][1];
                        sum1 += s[nb][2] + s[nb][3];
                    }
                } else if (u == 13) {
                    sum0 += __shfl_xor_sync(0xffffffffu, sum0, 1);
                    sum0 += __shfl_xor_sync(0xffffffffu, sum0, 2);
                    sum1 += __shfl_xor_sync(0xffffffffu, sum1, 1);
                    sum1 += __shfl_xor_sync(0xffffffffu, sum1, 2);
                    l0r = l0r * a0 + sum0;
                    l1r = l1r * a1 + sum1;
                } else if (u == 14) {
                    #pragma unroll
                    for (int j = 0; j < 8; ++j) {
                        acc[j][0] *= a0; acc[j][1] *= a0; acc[j][2] *= a1; acc[j][3] *= a1;
                    }
                } else {
                    #pragma unroll
                    for (int j = 8; j < 16; ++j) {
                        acc[j][0] *= a0; acc[j][1] *= a0; acc[j][2] *= a1; acc[j][3] *= a1;
                    }
                }
                // ------------------------------------------------------------

                ldsm4(bh0, ka0 + PLANE);
                ldsm4(bh1, ka1 + PLANE);
                mma_f16(sC[n0], qa_hi[kb0], bh0[0], bh0[1]);
                mma_f16(sC[n1], qa_hi[kb0], bh1[0], bh1[1]);
                mma_f16(sC[n0], qa_hi[kb1], bh0[2], bh0[3]);
                mma_f16(sC[n1], qa_hi[kb1], bh1[2], bh1[3]);
            }
        }
    };

    // ---- plain softmax (final tile) ----
    auto softmax_plain = [&](int ktp, float (&s)[8][4]) {
        const char* mrd0 = mrd_base + (ktp & 1) * MSKSTG;
        const char* mrd1 = mrd0 + 8 * MROW;
        float tm0 = NEG, tm1 = NEG;
        #pragma unroll
        for (int nb = 0; nb < 8; ++nb) {
            int c = (nb << 3) + ((lane & 3) << 1);
            uint32_t mm0 = *(const unsigned short*)(mrd0 + c);
            uint32_t mm1 = *(const unsigned short*)(mrd1 + c);
            s[nb][0] = (mm0 & 0xff) ? NEG : s[nb][0] * K2;
            s[nb][1] = (mm0 >> 8)   ? NEG : s[nb][1] * K2;
            s[nb][2] = (mm1 & 0xff) ? NEG : s[nb][2] * K2;
            s[nb][3] = (mm1 >> 8)   ? NEG : s[nb][3] * K2;
            tm0 = fmaxf(tm0, fmaxf(s[nb][0], s[nb][1]));
            tm1 = fmaxf(tm1, fmaxf(s[nb][2], s[nb][3]));
        }
        tm0 = fmaxf(tm0, __shfl_xor_sync(0xffffffffu, tm0, 1));
        tm0 = fmaxf(tm0, __shfl_xor_sync(0xffffffffu, tm0, 2));
        tm1 = fmaxf(tm1, __shfl_xor_sync(0xffffffffu, tm1, 1));
        tm1 = fmaxf(tm1, __shfl_xor_sync(0xffffffffu, tm1, 2));
        float mn0 = fmaxf(m0r, tm0), mn1 = fmaxf(m1r, tm1);
        float a0 = ex2f(m0r - mn0),  a1 = ex2f(m1r - mn1);
        float k0 = (mn0 > NEG) ? 1.f : 0.f;
        float k1 = (mn1 > NEG) ? 1.f : 0.f;
        float sum0 = 0.f, sum1 = 0.f;
        #pragma unroll
        for (int nb = 0; nb < 8; ++nb) {
            s[nb][0] = ex2f(s[nb][0] - mn0) * k0;
            s[nb][1] = ex2f(s[nb][1] - mn0) * k0;
            s[nb][2] = ex2f(s[nb][2] - mn1) * k1;
            s[nb][3] = ex2f(s[nb][3] - mn1) * k1;
            sum0 += s[nb][0] + s[nb][1];
            sum1 += s[nb][2] + s[nb][3];
        }
        sum0 += __shfl_xor_sync(0xffffffffu, sum0, 1);
        sum0 += __shfl_xor_sync(0xffffffffu, sum0, 2);
        sum1 += __shfl_xor_sync(0xffffffffu, sum1, 1);
        sum1 += __shfl_xor_sync(0xffffffffu, sum1, 2);
        l0r = l0r * a0 + sum0;
        l1r = l1r * a1 + sum1;
        m0r = mn0; m1r = mn1;
        #pragma unroll
        for (int j = 0; j < 16; ++j) {
            acc[j][0] *= a0; acc[j][1] *= a0; acc[j][2] *= a1; acc[j][3] *= a1;
        }
    };

    // ---- PV (single-term fp16) for tile ktp ----
    auto pv = [&](int ktp, float (&s)[8][4]) {
        const int vst = ktp - (ktp / 3) * 3;
        const uint32_t vfb = sm0 + (uint32_t)(SM_V + vst * PLANE) + vf_lane;
        #pragma unroll
        for (int kb = 0; kb < 4; ++kb) {
            uint32_t ph[4];
            ph[0] = pack_h2(s[2*kb][0],   s[2*kb][1]);
            ph[1] = pack_h2(s[2*kb][2],   s[2*kb][3]);
            ph[2] = pack_h2(s[2*kb+1][0], s[2*kb+1][1]);
            ph[3] = pack_h2(s[2*kb+1][2], s[2*kb+1][3]);
            uint32_t va = vfb + (uint32_t)(kb * 16 * RSB);
            #pragma unroll
            for (int jp = 0; jp < 8; ++jp) {
                uint32_t bh[4];
                ldsm4t(bh, va + jp * 32);
                mma_f16(acc[2*jp],   ph, bh[0], bh[1]);
                mma_f16(acc[2*jp+1], ph, bh[2], bh[3]);
            }
        }
    };

    // ---- one iteration ----
    auto iter = [&](int kt, float (&sC)[8][4], float (&sP)[8][4]) {
        CP_WAIT0();
        __syncthreads();
        if (kt + 1 < NIT) {
            fill_K(kt + 1);
            int vw = kt + 1; vw -= (vw / 3) * 3;
            fill_V(kt + 1, vw);
        }
        CP_COMMIT();

        char* mw = mskw0 + (kt & 1) * MSKSTG;
        #pragma unroll
        for (int j = 0; j < 8; ++j) *(uint32_t*)(mw + j * 4) = pk[j];
        __syncwarp();
        if (kt + 1 < NIT) ldgm(kt + 1);

        if (kt == 0) {
            qk_plain(0, sC);
        } else {
            fused(kt, sC, sP);      // QK(kt) + softmax(kt-1) interleaved
            pv(kt - 1, sP);
        }
    };

    #pragma unroll 1
    for (int kt2 = 0; kt2 < NIT; kt2 += 2) {
        iter(kt2,     sA, sB);
        iter(kt2 + 1, sB, sA);
    }
    softmax_plain(NIT - 1, sB);
    pv(NIT - 1, sB);

    // ---- epilogue ----
    float inv0 = (l0r > 0.f) ? (1.0f / l0r) : 0.f;
    float inv1 = (l1r > 0.f) ? (1.0f / l1r) : 0.f;
    const size_t gr0 = (size_t)b * LQ_ + q0 + r0l;
    const size_t gr1 = gr0 + 8;
    #pragma unroll
    for (int j = 0; j < 16; ++j) {
        int c = (j << 3) + ((lane & 3) << 1);
        float2 o0 = make_float2(acc[j][0] * inv0, acc[j][1] * inv0);
        float2 o1 = make_float2(acc[j][2] * inv1, acc[j][3] * inv1);
        *(float2*)(og + gr0 * DH + c) = o0;
        *(float2*)(og + gr1 * DH + c) = o1;
    }
}

} // namespace

extern "C" void kernel_launch(void* const* d_in, const int* in_sizes, int n_in,
                              void* d_out, int out_size) {
    const float* q = (const float*)d_in[0];
    const float* k = (const float*)d_in[1];
    const float* v = (const float*)d_in[2];
    const uint32_t* mask = (const uint32_t*)d_in[3];
    float* out = (float*)d_out;
    (void)in_sizes; (void)n_in; (void)out_size;

    conv_kernel<<<8192, 256>>>(k, v);

    cudaFuncSetAttribute(fa_r11_kernel, cudaFuncAttributeMaxDynamicSharedMemorySize, SM_TOT);
    dim3 grid(LQ_ / BR, B_);
    fa_r11_kernel<<<grid, NTH, SM_TOT>>>(q, mask, out);
}